// round 15
// baseline (speedup 1.0000x reference)
#include <cuda_runtime.h>
#include <cuda_fp16.h>
#include <stdint.h>

#define Bn 64
#define Dn 128
#define LCn 1024
#define LQn 128
#define NTn 8
#define NEGV (-1e30f)

__device__ float g_S [(size_t)Bn * LCn * LQn];
__device__ float g_Tp[(size_t)Bn * 4 * LQn * Dn];
__device__ float g_cp[Bn * NTn * LQn * 2];
__device__ unsigned char g_S1[(size_t)Bn * NTn * 32768];   // fp16 S1 tiles, swizzled

// smem: operand tiles in [0, 96K); small arrays at 96K; fp32 bounce OVERLAYS
// the operand region after the GEMM (operands dead by then).
#define A_HI 0
#define B_HI 32768
#define B_LO 65536
// k4 layout: A 32K | B1H 16K | B1L 16K | B2H 16K | B2L 16K
#define B1H 32768
#define B1L 49152
#define B2H 65536
#define B2L 81920
#define SMALL 98304
#define SMEM1 (SMALL + 6656)
#define SMEM3 (SMALL + 1536)
#define SMEM4 (SMALL + 1536)

__device__ __forceinline__ uint32_t s2u(const void* p) {
    uint32_t a;
    asm("{ .reg .u64 t; cvta.to.shared.u64 t, %1; cvt.u32.u64 %0, t; }" : "=r"(a) : "l"(p));
    return a;
}
// swizzled byte offset in a (rows x 128) half tile: 256B rows = 16 chunks;
// XOR low 3 chunk bits with (r&7), preserve chunk bit 3.
__device__ __forceinline__ uint32_t soff(int r, int k) {
    uint32_t c = (uint32_t)(k >> 3);
    uint32_t cs = (c & 8u) | ((c ^ (uint32_t)r) & 7u);
    return (uint32_t)(r << 8) + (cs << 4) + (uint32_t)((k & 7) << 1);
}
__device__ __forceinline__ uint32_t pack_hi(float v0, float v1) {
    __half2 h(__float2half_rn(v0), __float2half_rn(v1));
    return *(uint32_t*)&h;
}
__device__ __forceinline__ uint2 split_pair(float v0, float v1) {
    __half h0 = __float2half_rn(v0), h1 = __float2half_rn(v1);
    __half l0 = __float2half_rn(v0 - __half2float(h0));
    __half l1 = __float2half_rn(v1 - __half2float(h1));
    __half2 H(h0, h1), L(l0, l1);
    uint2 r; r.x = *(uint32_t*)&H; r.y = *(uint32_t*)&L; return r;
}
__device__ __forceinline__ void ld4(uint32_t addr, uint32_t r[4]) {
    asm volatile("ldmatrix.sync.aligned.m8n8.x4.shared.b16 {%0,%1,%2,%3}, [%4];"
        : "=r"(r[0]), "=r"(r[1]), "=r"(r[2]), "=r"(r[3]) : "r"(addr));
}
__device__ __forceinline__ void mma16(float c[4], const uint32_t a[4],
                                      uint32_t b0, uint32_t b1) {
    asm volatile("mma.sync.aligned.m16n8k16.row.col.f32.f16.f16.f32 "
        "{%0,%1,%2,%3}, {%4,%5,%6,%7}, {%8,%9}, {%0,%1,%2,%3};"
        : "+f"(c[0]), "+f"(c[1]), "+f"(c[2]), "+f"(c[3])
        : "r"(a[0]), "r"(a[1]), "r"(a[2]), "r"(a[3]), "r"(b0), "r"(b1));
}
// 128x128x128 GEMM, fp16 2-term (A hi, B hi+lo). Warp tile 32x64.
__device__ __forceinline__ void gemm2(uint32_t sbase, int m0, int n0, int lane,
                                      float acc[2][8][4])
{
    const int arow = lane & 15, achk = (lane >> 4) << 3;
    const int brow = ((lane >> 4) << 3) | (lane & 7);
    const int bchk = ((lane >> 3) & 1) << 3;
    #pragma unroll
    for (int ks = 0; ks < 8; ks++) {
        uint32_t ah[2][4], bh[16], bl[16];
        #pragma unroll
        for (int mi = 0; mi < 2; mi++)
            ld4(sbase + A_HI + soff(m0 + mi * 16 + arow, ks * 16 + achk), ah[mi]);
        #pragma unroll
        for (int p = 0; p < 4; p++) {
            uint32_t o = soff(n0 + p * 16 + brow, ks * 16 + bchk);
            ld4(sbase + B_HI + o, &bh[p * 4]);
            ld4(sbase + B_LO + o, &bl[p * 4]);
        }
        #pragma unroll
        for (int mi = 0; mi < 2; mi++)
            #pragma unroll
            for (int ni = 0; ni < 8; ni++) {
                mma16(acc[mi][ni], ah[mi], bh[ni * 2], bh[ni * 2 + 1]);
                mma16(acc[mi][ni], ah[mi], bl[ni * 2], bl[ni * 2 + 1]);
            }
    }
}
#define ZERO8(acc) { \
    _Pragma("unroll") for (int _i = 0; _i < 2; _i++) \
    _Pragma("unroll") for (int _j = 0; _j < 8; _j++) \
    _Pragma("unroll") for (int _k = 0; _k < 4; _k++) (acc)[_i][_j][_k] = 0.f; }
#define ZERO4(acc) { \
    _Pragma("unroll") for (int _i = 0; _i < 2; _i++) \
    _Pragma("unroll") for (int _j = 0; _j < 4; _j++) \
    _Pragma("unroll") for (int _k = 0; _k < 4; _k++) (acc)[_i][_j][_k] = 0.f; }

// =====================================================================
// K1: S tile via MMA; write g_S + column LSE partials + S1 (fp16 swizzled)
// =====================================================================
__global__ __launch_bounds__(256, 2) void k1_S(const float* __restrict__ C,
                                               const float* __restrict__ Q,
                                               const float* __restrict__ cmask,
                                               const float* __restrict__ qmask,
                                               const float* __restrict__ w)
{
    extern __shared__ char sb[];
    const uint32_t sb32 = s2u(sb);
    float* bounce = (float*)sb;              // overlays operands post-GEMM
    float* sc    = (float*)(sb + SMALL);
    float* sq    = (float*)(sb + SMALL + 512);
    float* wv    = (float*)(sb + SMALL + 1024);
    float* cmadd = (float*)(sb + SMALL + 2560);
    float* scp   = (float*)(sb + SMALL + 3072);   // reused for col-stat partials
    float* sqp   = (float*)(sb + SMALL + 4096);
    float* qmadd = (float*)(sb + SMALL + 5120);
    float* m1s   = (float*)(sb + SMALL + 5632);
    float* il1s  = (float*)(sb + SMALL + 6144);

    const int tid = threadIdx.x, wid = tid >> 5, lane = tid & 31;
    const int b = blockIdx.y, t = blockIdx.x, c0 = t * 128;

    for (int i = tid; i < 384; i += 256) wv[i] = w[i];
    if (tid < 128) {
        cmadd[tid] = (1.0f - cmask[b * LCn + c0 + tid]) * NEGV;
        qmadd[tid] = (1.0f - qmask[b * LQn + tid]) * NEGV;
    }
    __syncthreads();

    {   // A = (C*w_m)[c][d] hi + s_c partials
        const float* Cg = C + (size_t)b * Dn * LCn + c0;
        const int c = tid & 127;
        float av = 0.f;
        #pragma unroll 4
        for (int it = 0; it < 32; it++) {
            const int d2 = ((it * 256 + tid) >> 7) * 2;
            float v0 = Cg[(size_t)d2 * LCn + c];
            float v1 = Cg[(size_t)(d2 + 1) * LCn + c];
            av = fmaf(v0, wv[128 + d2], fmaf(v1, wv[129 + d2], av));
            *(uint32_t*)(sb + A_HI + soff(c, d2)) =
                pack_hi(v0 * wv[256 + d2], v1 * wv[257 + d2]);
        }
        scp[tid] = av;
    }
    {   // B = Q[q][d] hi/lo + s_q partials
        const float* Qg = Q + (size_t)b * Dn * LQn;
        const int q = tid & 127;
        float av = 0.f;
        #pragma unroll 4
        for (int it = 0; it < 32; it++) {
            const int d2 = ((it * 256 + tid) >> 7) * 2;
            float v0 = Qg[d2 * LQn + q];
            float v1 = Qg[(d2 + 1) * LQn + q];
            av = fmaf(v0, wv[d2], fmaf(v1, wv[d2 + 1], av));
            uint2 p = split_pair(v0, v1);
            uint32_t o = soff(q, d2);
            *(uint32_t*)(sb + B_HI + o) = p.x;
            *(uint32_t*)(sb + B_LO + o) = p.y;
        }
        sqp[tid] = av;
    }
    __syncthreads();
    if (tid < 128) sc[tid] = scp[tid] + scp[tid + 128];
    else { int q = tid & 127; sq[q] = sqp[q] + sqp[q + 128]; }
    __syncthreads();

    float acc[2][8][4];
    ZERO8(acc);
    const int m0 = (wid & 3) * 32, n0 = (wid >> 2) * 64;
    gemm2(sb32, m0, n0, lane, acc);
    __syncthreads();   // operands dead; bounce overlays them

    const int g = lane >> 2, l4 = lane & 3;
    #pragma unroll
    for (int mi = 0; mi < 2; mi++)
        #pragma unroll
        for (int ni = 0; ni < 8; ni++) {
            const int row = m0 + mi * 16 + g, col = n0 + ni * 8 + l4 * 2;
            float2 v;
            v.x = acc[mi][ni][0] + sc[row] + sq[col];
            v.y = acc[mi][ni][1] + sc[row] + sq[col + 1];
            *(float2*)&bounce[row * 132 + col] = v;
            v.x = acc[mi][ni][2] + sc[row + 8] + sq[col];
            v.y = acc[mi][ni][3] + sc[row + 8] + sq[col + 1];
            *(float2*)&bounce[(row + 8) * 132 + col] = v;
        }
    __syncthreads();

    // g_S write (for k3)
    float* gS = g_S + (size_t)(b * LCn + c0) * LQn;
    #pragma unroll 4
    for (int i = tid; i < 4096; i += 256) {
        int c = i >> 5, s = i & 31;
        *(float4*)(gS + c * LQn + s * 4) = *(float4*)(bounce + c * 132 + s * 4);
    }
    // Column (S2) partial stats: 256 threads over half-ranges, then combine
    {
        const int q = tid & 127, h = tid >> 7;
        const int cb = h * 64;
        float m = -3.4e38f;
        #pragma unroll 8
        for (int c = 0; c < 64; c++) m = fmaxf(m, bounce[(cb + c) * 132 + q] + cmadd[cb + c]);
        float l = 0.f;
        #pragma unroll 8
        for (int c = 0; c < 64; c++) l += __expf(bounce[(cb + c) * 132 + q] + cmadd[cb + c] - m);
        scp[tid] = m; sqp[tid] = l;
    }
    // Row (S1) stats: warp per row
    for (int c = wid; c < 128; c += 8) {
        float x0 = bounce[c * 132 + lane]      + qmadd[lane];
        float x1 = bounce[c * 132 + lane + 32] + qmadd[lane + 32];
        float x2 = bounce[c * 132 + lane + 64] + qmadd[lane + 64];
        float x3 = bounce[c * 132 + lane + 96] + qmadd[lane + 96];
        float m = fmaxf(fmaxf(x0, x1), fmaxf(x2, x3));
        #pragma unroll
        for (int off = 16; off; off >>= 1) m = fmaxf(m, __shfl_xor_sync(~0u, m, off));
        float l = __expf(x0 - m) + __expf(x1 - m) + __expf(x2 - m) + __expf(x3 - m);
        #pragma unroll
        for (int off = 16; off; off >>= 1) l += __shfl_xor_sync(~0u, l, off);
        if (lane == 0) { m1s[c] = m; il1s[c] = 1.0f / l; }
    }
    __syncthreads();

    if (tid < 128) {   // combine col-stat halves, write g_cp
        float ma = scp[tid], mb = scp[tid + 128];
        float la = sqp[tid], lb = sqp[tid + 128];
        float m = fmaxf(ma, mb);
        float l = la * __expf(ma - m) + lb * __expf(mb - m);
        float* cp = g_cp + ((b * NTn + t) * LQn + tid) * 2;
        cp[0] = m; cp[1] = l;
    }

    // S1 fp16 swizzled write (for k4's A operand)
    {
        unsigned char* dst = g_S1 + ((size_t)(b * NTn + t) << 15);
        const int q2 = (tid & 63) * 2;
        const float qa0 = qmadd[q2], qa1 = qmadd[q2 + 1];
        #pragma unroll 2
        for (int it = 0; it < 32; it++) {
            const int c = (it * 256 + tid) >> 6;
            float2 v = *(float2*)&bounce[c * 132 + q2];
            float m = m1s[c], il = il1s[c];
            *(uint32_t*)(dst + soff(c, q2)) =
                pack_hi(__expf(v.x + qa0 - m) * il, __expf(v.y + qa1 - m) * il);
        }
    }
}

// =====================================================================
// K3: partial T[q][d] over 2 c-tiles; column stats combined inline.
// =====================================================================
__global__ __launch_bounds__(256, 2) void k3_T(const float* __restrict__ C,
                                               const float* __restrict__ cmask)
{
    extern __shared__ char sb[];
    const uint32_t sb32 = s2u(sb);
    float* bounce = (float*)sb;
    float* m2    = (float*)(sb + SMALL);
    float* il2   = (float*)(sb + SMALL + 512);
    float* cmadd = (float*)(sb + SMALL + 1024);

    const int tid = threadIdx.x, wid = tid >> 5, lane = tid & 31;
    const int b = blockIdx.y, z = blockIdx.x;

    if (tid < 128) {   // inline colstat combine
        float mt[NTn], lt[NTn], m = -3.4e38f;
        #pragma unroll
        for (int t = 0; t < NTn; t++) {
            const float* cp = g_cp + ((b * NTn + t) * LQn + tid) * 2;
            mt[t] = cp[0]; lt[t] = cp[1]; m = fmaxf(m, mt[t]);
        }
        float l = 0.f;
        #pragma unroll
        for (int t = 0; t < NTn; t++) l += lt[t] * __expf(mt[t] - m);
        m2[tid] = m; il2[tid] = 1.0f / l;
    }
    __syncthreads();
    const int q = tid & 127;
    const float mq = m2[q], ilq = il2[q];

    float acc[2][8][4];
    ZERO8(acc);
    const int m0 = (wid & 3) * 32, n0 = (wid >> 2) * 64;

    for (int tt = 0; tt < 2; tt++) {
        const int t = z * 2 + tt;
        if (tid < 128) cmadd[tid] = (1.0f - cmask[b * LCn + t * 128 + tid]) * NEGV;
        __syncthreads();

        {   // A = S2[q][c] hi
            const float* gS = g_S + (size_t)(b * LCn + t * 128) * LQn;
            #pragma unroll 2
            for (int it = 0; it < 32; it++) {
                const int c2 = ((it * 256 + tid) >> 7) * 2;
                float e0 = __expf(gS[c2 * LQn + q]       + cmadd[c2]     - mq) * ilq;
                float e1 = __expf(gS[(c2 + 1) * LQn + q] + cmadd[c2 + 1] - mq) * ilq;
                *(uint32_t*)(sb + A_HI + soff(q, c2)) = pack_hi(e0, e1);
            }
        }
        {   // B = C[d][c] hi/lo
            const float* Cg = C + (size_t)b * Dn * LCn + t * 128;
            const int c2 = (tid & 63) * 2;
            #pragma unroll 2
            for (int it = 0; it < 32; it++) {
                const int d = (it * 256 + tid) >> 6;
                float2 v = *(const float2*)(Cg + (size_t)d * LCn + c2);
                uint2 p = split_pair(v.x, v.y);
                uint32_t o = soff(d, c2);
                *(uint32_t*)(sb + B_HI + o) = p.x;
                *(uint32_t*)(sb + B_LO + o) = p.y;
            }
        }
        __syncthreads();
        gemm2(sb32, m0, n0, lane, acc);
        __syncthreads();
    }

    const int g = lane >> 2, l4 = lane & 3;
    #pragma unroll
    for (int mi = 0; mi < 2; mi++)
        #pragma unroll
        for (int ni = 0; ni < 8; ni++) {
            const int row = m0 + mi * 16 + g, col = n0 + ni * 8 + l4 * 2;
            *(float2*)&bounce[row * 132 + col] = make_float2(acc[mi][ni][0], acc[mi][ni][1]);
            *(float2*)&bounce[(row + 8) * 132 + col] = make_float2(acc[mi][ni][2], acc[mi][ni][3]);
        }
    __syncthreads();
    float* tp = g_Tp + (size_t)(b * 4 + z) * LQn * Dn;
    #pragma unroll 4
    for (int i = tid; i < 4096; i += 256) {
        int r = i >> 5, s = i & 31;
        *(float4*)(tp + r * Dn + s * 4) = *(float4*)(bounce + r * 132 + s * 4);
    }
}

// =====================================================================
// K4: A = precomputed S1 tile (linear copy); dual GEMM on 128c x 64d half;
//     T summed from partials inline; fused 4-section epilogue.
// =====================================================================
__global__ __launch_bounds__(256, 2) void k4_final(const float* __restrict__ C,
                                                   const float* __restrict__ Q,
                                                   float* __restrict__ out)
{
    extern __shared__ char sb[];
    const uint32_t sb32 = s2u(sb);

    const int tid = threadIdx.x, wid = tid >> 5, lane = tid & 31;
    const int b = blockIdx.y, t = blockIdx.x, c0 = t * 128;
    const int dh0 = blockIdx.z * 64;

    {   // A = S1 tile: linear 32KB copy (already fp16 + swizzled)
        const uint4* asrc = (const uint4*)(g_S1 + ((size_t)(b * NTn + t) << 15));
        uint4* adst = (uint4*)(sb + A_HI);
        #pragma unroll 2
        for (int i = tid; i < 2048; i += 256) adst[i] = asrc[i];
    }
    {   // B1 = Q[dh0+d][q] hi/lo, 64 rows x 128 q
        const float* Qg = Q + (size_t)b * Dn * LQn + (size_t)dh0 * LQn;
        const int q2 = (tid & 63) * 2;
        #pragma unroll 2
        for (int it = 0; it < 16; it++) {
            const int d = (it * 256 + tid) >> 6;
            float2 v = *(const float2*)(Qg + d * LQn + q2);
            uint2 p = split_pair(v.x, v.y);
            uint32_t o = soff(d, q2);
            *(uint32_t*)(sb + B1H + o) = p.x;
            *(uint32_t*)(sb + B1L + o) = p.y;
        }
    }
    {   // B2[d][q] = sum_z Tp[z][q][dh0+d] hi/lo (transpose + reduce)
        const float* tp = g_Tp + (size_t)b * 4 * LQn * Dn + dh0;
        #pragma unroll 2
        for (int it = 0; it < 16; it++) {
            const int i = it * 256 + tid;
            const int d2 = (i & 31) * 2;
            const int qq = i >> 5;
            float2 v0 = *(const float2*)(tp + qq * Dn + d2);
            float2 v1 = *(const float2*)(tp + 16384 + qq * Dn + d2);
            float2 v2 = *(const float2*)(tp + 32768 + qq * Dn + d2);
            float2 v3 = *(const float2*)(tp + 49152 + qq * Dn + d2);
            float sx = (v0.x + v1.x) + (v2.x + v3.x);
            float sy = (v0.y + v1.y) + (v2.y + v3.y);
            __half h0 = __float2half_rn(sx);
            __half l0 = __float2half_rn(sx - __half2float(h0));
            __half h1 = __float2half_rn(sy);
            __half l1 = __float2half_rn(sy - __half2float(h1));
            uint32_t o0 = soff(d2, qq), o1 = soff(d2 + 1, qq);
            *(__half*)(sb + B2H + o0) = h0;
            *(__half*)(sb + B2L + o0) = l0;
            *(__half*)(sb + B2H + o1) = h1;
            *(__half*)(sb + B2L + o1) = l1;
        }
    }
    __syncthreads();

    // Dual GEMM, warp tile 32c x 32d, shared A fragments
    float acc1[2][4][4], acc2[2][4][4];
    ZERO4(acc1); ZERO4(acc2);
    const int m0 = (wid & 3) * 32, n0 = (wid >> 2) * 32;
    {
        const int arow = lane & 15, achk = (lane >> 4) << 3;
        const int brow = ((lane >> 4) << 3) | (lane & 7);
        const int bchk = ((lane >> 3) & 1) << 3;
        #pragma unroll
        for (int ks = 0; ks < 8; ks++) {
            uint32_t ah[2][4];
            #pragma unroll
            for (int mi = 0; mi < 2; mi++)
                ld4(sb32 + A_HI + soff(m0 + mi * 16 + arow, ks * 16 + achk), ah[mi]);
            uint32_t b1h[8], b1l[8], b2h[8], b2l[8];
            #pragma unroll
            for (int p = 0; p < 2; p++) {
                uint32_t o = soff(n0 + p * 16 + brow, ks * 16 + bchk);
                ld4(sb32 + B1H + o, &b1h[p * 4]);
                ld4(sb32 + B1L + o, &b1l[p * 4]);
                ld4(sb32 + B2H + o, &b2h[p * 4]);
                ld4(sb32 + B2L + o, &b2l[p * 4]);
            }
            #pragma unroll
            for (int mi = 0; mi < 2; mi++)
                #pragma unroll
                for (int ni = 0; ni < 4; ni++) {
                    mma16(acc1[mi][ni], ah[mi], b1h[ni * 2], b1h[ni * 2 + 1]);
                    mma16(acc1[mi][ni], ah[mi], b1l[ni * 2], b1l[ni * 2 + 1]);
                    mma16(acc2[mi][ni], ah[mi], b2h[ni * 2], b2h[ni * 2 + 1]);
                    mma16(acc2[mi][ni], ah[mi], b2l[ni * 2], b2l[ni * 2 + 1]);
                }
        }
    }
    __syncthreads();   // operands dead; bounces overlay

    float* bnc1 = (float*)sb;                  // [d 64][c 132]
    float* bnc2 = (float*)(sb + 36864);
    const int g = lane >> 2, l4 = lane & 3;
    #pragma unroll
    for (int mi = 0; mi < 2; mi++)
        #pragma unroll
        for (int ni = 0; ni < 4; ni++) {
            const int row = m0 + mi * 16 + g, col = n0 + ni * 8 + l4 * 2;
            bnc1[col * 132 + row]           = acc1[mi][ni][0];
            bnc1[(col + 1) * 132 + row]     = acc1[mi][ni][1];
            bnc1[col * 132 + row + 8]       = acc1[mi][ni][2];
            bnc1[(col + 1) * 132 + row + 8] = acc1[mi][ni][3];
            bnc2[col * 132 + row]           = acc2[mi][ni][0];
            bnc2[(col + 1) * 132 + row]     = acc2[mi][ni][1];
            bnc2[col * 132 + row + 8]       = acc2[mi][ni][2];
            bnc2[(col + 1) * 132 + row + 8] = acc2[mi][ni][3];
        }
    __syncthreads();

    // Fused epilogue: this CTA's 64 d-rows of all 4 sections, one C read
    float* outB = out + (size_t)b * 4 * Dn * LCn;
    const float* Cb = C + (size_t)b * Dn * LCn;
    #pragma unroll 2
    for (int i = tid; i < 2048; i += 256) {
        int dl = i >> 5, c4 = (i & 31) * 4;
        int d = dh0 + dl;
        float4 a  = *(float4*)(bnc1 + dl * 132 + c4);
        float4 bt = *(float4*)(bnc2 + dl * 132 + c4);
        float4 cv = *(const float4*)(Cb + (size_t)d * LCn + c0 + c4);
        *(float4*)(outB + (size_t)d * LCn + c0 + c4) = cv;
        *(float4*)(outB + (size_t)(128 + d) * LCn + c0 + c4) = a;
        *(float4*)(outB + (size_t)(256 + d) * LCn + c0 + c4) =
            make_float4(cv.x * a.x, cv.y * a.y, cv.z * a.z, cv.w * a.w);
        *(float4*)(outB + (size_t)(384 + d) * LCn + c0 + c4) =
            make_float4(cv.x * bt.x, cv.y * bt.y, cv.z * bt.z, cv.w * bt.w);
    }
}

// ---------------------------------------------------------------------------
extern "C" void kernel_launch(void* const* d_in, const int* in_sizes, int n_in,
                              void* d_out, int out_size)
{
    const float* C     = (const float*)d_in[0];
    const float* Q     = (const float*)d_in[1];
    const float* cmask = (const float*)d_in[2];
    const float* qmask = (const float*)d_in[3];
    const float* w     = (const float*)d_in[4];
    float* out = (float*)d_out;

    cudaFuncSetAttribute(k1_S,     cudaFuncAttributeMaxDynamicSharedMemorySize, SMEM1);
    cudaFuncSetAttribute(k3_T,     cudaFuncAttributeMaxDynamicSharedMemorySize, SMEM3);
    cudaFuncSetAttribute(k4_final, cudaFuncAttributeMaxDynamicSharedMemorySize, SMEM4);

    k1_S<<<dim3(NTn, Bn), 256, SMEM1>>>(C, Q, cmask, qmask, w);
    k3_T<<<dim3(4, Bn), 256, SMEM3>>>(C, cmask);
    k4_final<<<dim3(NTn, Bn, 2), 256, SMEM4>>>(C, Q, out);
}